// round 12
// baseline (speedup 1.0000x reference)
#include <cuda_runtime.h>
#include <cuda_bf16.h>
#include <math.h>
#include <stdint.h>

#define NN 30000
#define EE 240000
#define GG 1500
#define EMB 300
#define EMB2 600
#define TASKS 12
#define GAMMA 0.4f
#define INV_T 5.0f   // 1 / T_CON

#define KP3 928      // padded 3*300 (29 K-stages of 32)
#define KP6 1824     // padded 3*600 (57 K-stages of 32)
#define NPAD1 640    // padded N=600
#define NPAD2 384    // padded N=300

// ---------------- scratch (static device allocations; zero-initialized) ----------------
__device__ float d_xfeat[NN * EMB];
__device__ float d_hb[NN * EMB];
__device__ float d_xr[NN * EMB];
__device__ float d_agg[NN * EMB];
__device__ float d_tmp[NN * EMB2];
__device__ float d_gate[NN];
__device__ float d_hr[GG * EMB];
__device__ float d_henv[GG * EMB];
__device__ float d_hout[GG * EMB];
__device__ float d_henvT[EMB * GG];
__device__ float d_S[GG * GG];
__device__ float d_na[GG], d_nb[GG], d_nc[GG], d_posdot[GG];
__device__ float d_rnum[GG], d_envnum[GG];
__device__ float d_rowsum[GG];
__device__ float d_hin[2 * GG * EMB];
__device__ __nv_bfloat16 d_AS[(size_t)NN * KP3];
__device__ __nv_bfloat16 d_tmpS[(size_t)NN * KP6];
__device__ __nv_bfloat16 d_WS1all[(size_t)9 * KP3 * NPAD1];
__device__ __nv_bfloat16 d_WS2all[(size_t)7 * KP6 * NPAD2];

__device__ __forceinline__ uint32_t pack_bf2(__nv_bfloat16 lo, __nv_bfloat16 hi) {
    return ((uint32_t)__bfloat16_as_ushort(hi) << 16) | (uint32_t)__bfloat16_as_ushort(lo);
}

// ---------------- node encoder ----------------
__global__ void enc_kernel(const float* __restrict__ x, const float* __restrict__ W,
                           const float* __restrict__ b, float* __restrict__ out) {
    int idx = blockIdx.x * blockDim.x + threadIdx.x;
    if (idx >= NN * EMB) return;
    int i = idx / EMB, j = idx % EMB;
    const float* xr = x + i * 9;
    float acc = b[j];
#pragma unroll
    for (int k = 0; k < 9; k++) acc += xr[k] * W[k * EMB + j];
    out[idx] = acc;
}

// ------------- edge message passing (float4): agg[dst] += relu(x[src] + ea@We + be) -------------
__global__ void edge_mp(const float* __restrict__ x, float* __restrict__ agg,
                        const int* __restrict__ src, const int* __restrict__ dst,
                        const float* __restrict__ ea, const float* __restrict__ We,
                        const float* __restrict__ be) {
    int w = (blockIdx.x * blockDim.x + threadIdx.x) >> 5;
    int lane = threadIdx.x & 31;
    if (w >= EE) return;
    int s = src[w], d = dst[w];
    float a0 = ea[w * 3 + 0], a1 = ea[w * 3 + 1], a2 = ea[w * 3 + 2];
    const float4* xs4 = (const float4*)(x + (size_t)s * EMB);
    const float4* We0 = (const float4*)We;          // row 0
    const float4* We1 = (const float4*)(We + EMB);  // row 1
    const float4* We2 = (const float4*)(We + 2 * EMB);
    const float4* be4 = (const float4*)be;
    float* ag = agg + (size_t)d * EMB;
    for (int k4 = lane; k4 < EMB / 4; k4 += 32) {
        float4 xv = xs4[k4];
        float4 w0 = We0[k4], w1 = We1[k4], w2 = We2[k4], bb = be4[k4];
        float m0 = xv.x + fmaf(a0, w0.x, fmaf(a1, w1.x, fmaf(a2, w2.x, bb.x)));
        float m1 = xv.y + fmaf(a0, w0.y, fmaf(a1, w1.y, fmaf(a2, w2.y, bb.y)));
        float m2 = xv.z + fmaf(a0, w0.z, fmaf(a1, w1.z, fmaf(a2, w2.z, bb.z)));
        float m3 = xv.w + fmaf(a0, w0.w, fmaf(a1, w1.w, fmaf(a2, w2.w, bb.w)));
        m0 = fmaxf(m0, 0.f); m1 = fmaxf(m1, 0.f);
        m2 = fmaxf(m2, 0.f); m3 = fmaxf(m3, 0.f);
        int c = k4 * 4;
        atomicAdd(&ag[c + 0], m0);
        atomicAdd(&ag[c + 1], m1);
        atomicAdd(&ag[c + 2], m2);
        atomicAdd(&ag[c + 3], m3);
    }
}

// ---------------- splits (float4 / uint2) ----------------
// A' row (K=300): [h | l | h]; pads stay zero. base optional (fused GIN self-term).
__global__ void splitAB_kernel(const float* __restrict__ in, const float* __restrict__ base,
                               int M, __nv_bfloat16* __restrict__ out) {
    int idx = blockIdx.x * blockDim.x + threadIdx.x;
    if (idx >= M * (EMB / 4)) return;
    int m = idx / (EMB / 4), q4 = idx % (EMB / 4);
    float4 v = ((const float4*)(in))[(size_t)m * (EMB / 4) + q4];
    if (base) {
        float4 b = ((const float4*)(base))[(size_t)m * (EMB / 4) + q4];
        v.x += b.x; v.y += b.y; v.z += b.z; v.w += b.w;
    }
    float vv[4] = {v.x, v.y, v.z, v.w};
    __nv_bfloat16 h[4], l[4];
#pragma unroll
    for (int i = 0; i < 4; i++) {
        h[i] = __float2bfloat16(vv[i]);
        l[i] = __float2bfloat16(vv[i] - __bfloat162float(h[i]));
    }
    uint2 H, L;
    H.x = pack_bf2(h[0], h[1]); H.y = pack_bf2(h[2], h[3]);
    L.x = pack_bf2(l[0], l[1]); L.y = pack_bf2(l[2], l[3]);
    __nv_bfloat16* row = out + (size_t)m * KP3;
    int c = q4 * 4;
    *(uint2*)(row + c) = H;
    *(uint2*)(row + 300 + c) = L;
    *(uint2*)(row + 600 + c) = H;
}

// batched weight splits. B' rows [h; h; l] (3K), cols padded Npad.
__global__ void splitW1_all(const float* __restrict__ W1g, const float* __restrict__ W1r,
                            const float* __restrict__ Wg1, const float* __restrict__ Wp1,
                            __nv_bfloat16* __restrict__ WS) {
    int mat = blockIdx.y;
    const float* W = (mat < 5) ? (W1g + (size_t)mat * 300 * 600)
                   : (mat < 7) ? (W1r + (size_t)(mat - 5) * 300 * 600)
                   : (mat == 7) ? Wg1 : Wp1;
    __nv_bfloat16* dst = WS + (size_t)mat * KP3 * NPAD1;
    int idx = blockIdx.x * blockDim.x + threadIdx.x;
    if (idx >= 900 * NPAD1) return;
    int k3 = idx / NPAD1, n = idx % NPAD1;
    __nv_bfloat16 r = __float2bfloat16(0.f);
    if (n < 600) {
        int seg = k3 / 300, k = k3 % 300;
        float v = W[(size_t)k * 600 + n];
        __nv_bfloat16 h = __float2bfloat16(v);
        r = (seg < 2) ? h : __float2bfloat16(v - __bfloat162float(h));
    }
    dst[(size_t)k3 * NPAD1 + n] = r;
}
__global__ void splitW2_all(const float* __restrict__ W2g, const float* __restrict__ W2r,
                            __nv_bfloat16* __restrict__ WS) {
    int mat = blockIdx.y;
    const float* W = (mat < 5) ? (W2g + (size_t)mat * 600 * 300)
                               : (W2r + (size_t)(mat - 5) * 600 * 300);
    __nv_bfloat16* dst = WS + (size_t)mat * KP6 * NPAD2;
    int idx = blockIdx.x * blockDim.x + threadIdx.x;
    if (idx >= 1800 * NPAD2) return;
    int k3 = idx / NPAD2, n = idx % NPAD2;
    __nv_bfloat16 r = __float2bfloat16(0.f);
    if (n < 300) {
        int seg = k3 / 600, k = k3 % 600;
        float v = W[(size_t)k * 300 + n];
        __nv_bfloat16 h = __float2bfloat16(v);
        r = (seg < 2) ? h : __float2bfloat16(v - __bfloat162float(h));
    }
    dst[(size_t)k3 * NPAD2 + n] = r;
}

// ---------------- epilogue flags ----------------
// ep: 0 = +bias,relu ; 1 = +bias,relu,+resid ; 2 = +bias,+resid ;
//     4 = +bias,relu -> split only ; 5 = +bias,+resid -> C AND split
__device__ __forceinline__ void epilogue_elem(int ep, float v, int r, int c, int N,
                                              const float* resid, float* C,
                                              __nv_bfloat16* outS, int ldS) {
    if (ep == 0 || ep == 1 || ep == 4) v = fmaxf(v, 0.f);
    if (ep == 1 || ep == 2 || ep == 5) v += resid[(size_t)r * N + c];
    if (ep == 4 || ep == 5) {
        __nv_bfloat16 h = __float2bfloat16(v);
        __nv_bfloat16 l = __float2bfloat16(v - __bfloat162float(h));
        __nv_bfloat16* rowS = outS + (size_t)r * ldS;
        rowS[c] = h; rowS[N + c] = l; rowS[2 * N + c] = h;
    }
    if (ep != 4) C[(size_t)r * N + c] = v;
}

// ============================================================================
// bf16 HMMA GEMM, 3-stage cp.async ring. Tile 128x128, 8 warps. (R8 config)
// ============================================================================
#define HA_STR 40
#define HB_STR 136
#define HA_BYTES (128 * HA_STR * 2)
#define HSTAGE_BYTES (HA_BYTES + 32 * HB_STR * 2)
#define HG_SMEM (3 * HSTAGE_BYTES)

__global__ __launch_bounds__(256, 2)
void hgemm(const __nv_bfloat16* __restrict__ A, int lda,
           const __nv_bfloat16* __restrict__ B, int ldb,
           const float* __restrict__ bias, float* __restrict__ C,
           const float* __restrict__ resid,
           __nv_bfloat16* __restrict__ outS, int ldS,
           int M, int N, int K3, int ep) {
    extern __shared__ char hsm[];
    const int tid = threadIdx.x;
    const int wid = tid >> 5, lane = tid & 31;
    const int grp = lane >> 2, tig = lane & 3;
    const int wm = (wid >> 2) * 64, wn = (wid & 3) * 32;
    const int lrow = lane & 15, lcol = (lane >> 4) * 8;
    const int row0 = blockIdx.y * 128;
    const int col0 = blockIdx.x * 128;
    const int nk = K3 / 32;

    auto loadTile = [&](int t) {
        char* stA = hsm + (t % 3) * HSTAGE_BYTES;
        char* stB = stA + HA_BYTES;
        const int kb = t * 32;
#pragma unroll
        for (int i = 0; i < 2; i++) {
            int c = tid * 2 + i;
            int ar = c >> 2, ak = (c & 3) * 8;
            int gr = row0 + ar;
            const __nv_bfloat16* gp = A + (size_t)(gr < M ? gr : M - 1) * lda + kb + ak;
            uint32_t sp = (uint32_t)__cvta_generic_to_shared(stA + (ar * HA_STR + ak) * 2);
            int sz = (gr < M) ? 16 : 0;
            asm volatile("cp.async.cg.shared.global [%0], [%1], 16, %2;"
                         :: "r"(sp), "l"(gp), "r"(sz) : "memory");
        }
#pragma unroll
        for (int i = 0; i < 2; i++) {
            int c = tid * 2 + i;
            int br = c >> 4, bn = (c & 15) * 8;
            const __nv_bfloat16* gp = B + (size_t)(kb + br) * ldb + col0 + bn;
            uint32_t sp = (uint32_t)__cvta_generic_to_shared(stB + (br * HB_STR + bn) * 2);
            asm volatile("cp.async.cg.shared.global [%0], [%1], 16, 16;"
                         :: "r"(sp), "l"(gp) : "memory");
        }
        asm volatile("cp.async.commit_group;" ::: "memory");
    };

    float acc[4][4][4];
#pragma unroll
    for (int i = 0; i < 4; i++)
#pragma unroll
        for (int j = 0; j < 4; j++)
#pragma unroll
            for (int q = 0; q < 4; q++) acc[i][j][q] = 0.f;

    loadTile(0);
    if (nk > 1) loadTile(1);

    for (int t = 0; t < nk; t++) {
        if (t + 1 < nk)
            asm volatile("cp.async.wait_group 1;" ::: "memory");
        else
            asm volatile("cp.async.wait_group 0;" ::: "memory");
        __syncthreads();
        if (t + 2 < nk) loadTile(t + 2);

        char* stA = hsm + (t % 3) * HSTAGE_BYTES;
        __nv_bfloat16* Asm = (__nv_bfloat16*)stA;
        __nv_bfloat16* Bsm = (__nv_bfloat16*)(stA + HA_BYTES);
#pragma unroll
        for (int ks = 0; ks < 2; ks++) {
            const int k0 = ks * 16;
            uint32_t af[4][4], bf[4][2];
#pragma unroll
            for (int mt = 0; mt < 4; mt++) {
                uint32_t sa = (uint32_t)__cvta_generic_to_shared(
                    &Asm[(wm + mt * 16 + lrow) * HA_STR + k0 + lcol]);
                asm volatile(
                    "ldmatrix.sync.aligned.m8n8.x4.shared.b16 {%0,%1,%2,%3}, [%4];"
                    : "=r"(af[mt][0]), "=r"(af[mt][1]), "=r"(af[mt][2]), "=r"(af[mt][3])
                    : "r"(sa));
            }
#pragma unroll
            for (int ng = 0; ng < 2; ng++) {
                uint32_t sb = (uint32_t)__cvta_generic_to_shared(
                    &Bsm[(k0 + lrow) * HB_STR + wn + ng * 16 + lcol]);
                uint32_t r0, r1, r2, r3;
                asm volatile(
                    "ldmatrix.sync.aligned.m8n8.x4.trans.shared.b16 {%0,%1,%2,%3}, [%4];"
                    : "=r"(r0), "=r"(r1), "=r"(r2), "=r"(r3) : "r"(sb));
                bf[ng * 2][0] = r0; bf[ng * 2][1] = r1;
                bf[ng * 2 + 1][0] = r2; bf[ng * 2 + 1][1] = r3;
            }
#pragma unroll
            for (int mt = 0; mt < 4; mt++)
#pragma unroll
                for (int nt = 0; nt < 4; nt++)
                    asm volatile(
                        "mma.sync.aligned.m16n8k16.row.col.f32.bf16.bf16.f32 "
                        "{%0,%1,%2,%3}, {%4,%5,%6,%7}, {%8,%9}, {%0,%1,%2,%3};"
                        : "+f"(acc[mt][nt][0]), "+f"(acc[mt][nt][1]),
                          "+f"(acc[mt][nt][2]), "+f"(acc[mt][nt][3])
                        : "r"(af[mt][0]), "r"(af[mt][1]), "r"(af[mt][2]), "r"(af[mt][3]),
                          "r"(bf[nt][0]), "r"(bf[nt][1]));
        }
    }

#pragma unroll
    for (int mt = 0; mt < 4; mt++)
#pragma unroll
        for (int nt = 0; nt < 4; nt++) {
            int rA = row0 + wm + mt * 16 + grp;
            int cA = col0 + wn + nt * 8 + 2 * tig;
#pragma unroll
            for (int half = 0; half < 2; half++) {
                int r = rA + half * 8;
                if (r >= M) continue;
#pragma unroll
                for (int q = 0; q < 2; q++) {
                    int c = cA + q;
                    if (c >= N) continue;
                    epilogue_elem(ep, acc[mt][nt][half * 2 + q] + bias[c],
                                  r, c, N, resid, C, outS, ldS);
                }
            }
        }
}

// ---------------- fp32 SGEMM (S matrix only) ----------------
#define BM 128
#define BN 128
#define BK 16
__global__ __launch_bounds__(256, 2)
void sgemm_opt(const float* __restrict__ A, const float* __restrict__ B,
               float* __restrict__ C, int M, int N, int K) {
    __shared__ float As[2][BK][BM + 4];
    __shared__ float Bs[2][BK][BN];
    const int tid = threadIdx.x;
    const int row0 = blockIdx.y * BM;
    const int col0 = blockIdx.x * BN;
    const int tx = tid & 15, ty = tid >> 4;
    const int ar = tid >> 1, ak0 = (tid & 1) * 8;
    const int br = tid >> 5, bc = (tid & 31) * 4;
    float4 aReg[2], bReg[2];
    const int gr = row0 + ar;
    const bool arow_ok = (gr < M);
    const float* Arow = A + (size_t)gr * K;

    auto loadA = [&](int k0) {
#pragma unroll
        for (int v = 0; v < 2; v++) {
            int k = k0 + ak0 + v * 4;
            float4 t = make_float4(0.f, 0.f, 0.f, 0.f);
            if (arow_ok) {
                if (k + 3 < K) t = *(const float4*)(Arow + k);
                else {
                    float u[4] = {0.f, 0.f, 0.f, 0.f};
#pragma unroll
                    for (int q = 0; q < 4; q++) if (k + q < K) u[q] = Arow[k + q];
                    t = make_float4(u[0], u[1], u[2], u[3]);
                }
            }
            aReg[v] = t;
        }
    };
    auto loadB = [&](int k0) {
#pragma unroll
        for (int v = 0; v < 2; v++) {
            int k = k0 + br + v * 8;
            int c = col0 + bc;
            float4 t = make_float4(0.f, 0.f, 0.f, 0.f);
            if (k < K) {
                const float* Brow = B + (size_t)k * N;
                if (c + 3 < N) t = *(const float4*)(Brow + c);
                else {
                    float u[4] = {0.f, 0.f, 0.f, 0.f};
#pragma unroll
                    for (int q = 0; q < 4; q++) if (c + q < N) u[q] = Brow[c + q];
                    t = make_float4(u[0], u[1], u[2], u[3]);
                }
            }
            bReg[v] = t;
        }
    };
    auto storeAB = [&](int buf) {
#pragma unroll
        for (int v = 0; v < 2; v++) {
            As[buf][ak0 + v * 4 + 0][ar] = aReg[v].x;
            As[buf][ak0 + v * 4 + 1][ar] = aReg[v].y;
            As[buf][ak0 + v * 4 + 2][ar] = aReg[v].z;
            As[buf][ak0 + v * 4 + 3][ar] = aReg[v].w;
            *(float4*)&Bs[buf][br + v * 8][bc] = bReg[v];
        }
    };

    float acc[8][8] = {};
    const int nk = (K + BK - 1) / BK;
    loadA(0); loadB(0); storeAB(0);
    __syncthreads();
    for (int t = 0; t < nk; t++) {
        const int buf = t & 1;
        if (t + 1 < nk) { loadA((t + 1) * BK); loadB((t + 1) * BK); }
#pragma unroll
        for (int kk = 0; kk < BK; kk++) {
            float a[8], b[8];
            *(float4*)&a[0] = *(const float4*)&As[buf][kk][ty * 8];
            *(float4*)&a[4] = *(const float4*)&As[buf][kk][ty * 8 + 4];
            *(float4*)&b[0] = *(const float4*)&Bs[buf][kk][tx * 8];
            *(float4*)&b[4] = *(const float4*)&Bs[buf][kk][tx * 8 + 4];
#pragma unroll
            for (int i = 0; i < 8; i++)
#pragma unroll
                for (int j = 0; j < 8; j++) acc[i][j] = fmaf(a[i], b[j], acc[i][j]);
        }
        if (t + 1 < nk) { storeAB(buf ^ 1); __syncthreads(); }
    }
#pragma unroll
    for (int i = 0; i < 8; i++) {
        int r = row0 + ty * 8 + i;
        if (r >= M) continue;
#pragma unroll
        for (int j = 0; j < 8; j++) {
            int c = col0 + tx * 8 + j;
            if (c >= N) continue;
            C[(size_t)r * N + c] = acc[i][j];
        }
    }
}

// ---------------- gate ----------------
__global__ void gate_kernel(const float* __restrict__ tmp, const float* __restrict__ Wg2,
                            const float* __restrict__ bg2, const float* __restrict__ gumbel,
                            float* __restrict__ gate) {
    int w = (blockIdx.x * blockDim.x + threadIdx.x) >> 5;
    int lane = threadIdx.x & 31;
    if (w >= NN) return;
    const float* row = tmp + (size_t)w * EMB2;
    float a0 = 0.f, a1 = 0.f;
    for (int k = lane; k < EMB2; k += 32) {
        float v = row[k];
        a0 = fmaf(v, Wg2[2 * k + 0], a0);
        a1 = fmaf(v, Wg2[2 * k + 1], a1);
    }
    for (int o = 16; o; o >>= 1) {
        a0 += __shfl_down_sync(0xffffffffu, a0, o);
        a1 += __shfl_down_sync(0xffffffffu, a1, o);
    }
    if (lane == 0) {
        float z0 = a0 + bg2[0] + gumbel[2 * w + 0];
        float z1 = a1 + bg2[1] + gumbel[2 * w + 1];
        gate[w] = 1.f / (1.f + expf(z0 - z1));
    }
}

// ---------------- per-graph segment means (batch sorted) ----------------
__device__ __forceinline__ int lower_bound_batch(const int* __restrict__ batch, int val) {
    int lo = 0, hi = NN;
    while (lo < hi) {
        int mid = (lo + hi) >> 1;
        if (batch[mid] < val) lo = mid + 1; else hi = mid;
    }
    return lo;
}

__global__ void segment_kernel(const float* __restrict__ hb, const float* __restrict__ gate,
                               const int* __restrict__ batch,
                               float* __restrict__ hr, float* __restrict__ henv,
                               float* __restrict__ hout, float* __restrict__ rnum,
                               float* __restrict__ envnum) {
    int g = blockIdx.x;
    int s = lower_bound_batch(batch, g);
    int e = lower_bound_batch(batch, g + 1);
    float cnt = fmaxf((float)(e - s), 1.f);
    int tid = threadIdx.x;
    if (tid < EMB) {
        float ar = 0.f, ae = 0.f, ao = 0.f;
        for (int n = s; n < e; n++) {
            float h = hb[(size_t)n * EMB + tid];
            float gt = gate[n];
            ar = fmaf(gt, h, ar);
            ae = fmaf(1.f - gt, h, ae);
            ao += h;
        }
        hr[g * EMB + tid] = ar / cnt;
        henv[g * EMB + tid] = ae / cnt;
        hout[g * EMB + tid] = ao / cnt;
    }
    __shared__ float sh[512];
    float gs = 0.f;
    for (int n = s + tid; n < e; n += blockDim.x) gs += gate[n];
    sh[tid] = gs;
    __syncthreads();
    for (int o = 256; o; o >>= 1) {
        if (tid < o) sh[tid] += sh[tid + o];
        __syncthreads();
    }
    if (tid == 0) {
        rnum[g] = sh[0] + 1e-8f;
        envnum[g] = ((float)(e - s) - sh[0]) + 1e-8f;
    }
}

__global__ void norm_kernel(const float* __restrict__ hr, const float* __restrict__ henv,
                            const float* __restrict__ hout, float* __restrict__ na,
                            float* __restrict__ nb, float* __restrict__ nc,
                            float* __restrict__ posdot) {
    int g = blockIdx.x, tid = threadIdx.x;
    float s1 = 0, s2 = 0, s3 = 0, s4 = 0;
    for (int d = tid; d < EMB; d += 128) {
        float a = hr[g * EMB + d], o = hout[g * EMB + d], ev = henv[g * EMB + d];
        s1 = fmaf(a, a, s1); s2 = fmaf(o, o, s2); s3 = fmaf(ev, ev, s3); s4 = fmaf(a, o, s4);
    }
    __shared__ float sh[128];
    auto red = [&](float v) -> float {
        sh[tid] = v; __syncthreads();
        for (int o = 64; o; o >>= 1) { if (tid < o) sh[tid] += sh[tid + o]; __syncthreads(); }
        float r = sh[0]; __syncthreads();
        return r;
    };
    float r1 = red(s1), r2 = red(s2), r3 = red(s3), r4 = red(s4);
    if (tid == 0) {
        na[g] = sqrtf(r1); nb[g] = sqrtf(r2); nc[g] = sqrtf(r3); posdot[g] = r4;
    }
}

__global__ void lossreg_kernel(const float* __restrict__ rnum, const float* __restrict__ envnum,
                               float* __restrict__ out) {
    int tid = threadIdx.x;
    float local = 0.f;
    for (int g = tid; g < GG; g += 512) {
        float r = rnum[g], ev = envnum[g];
        local += fabsf(r / (r + ev) - GAMMA);
    }
    __shared__ float sh[512];
    sh[tid] = local; __syncthreads();
    for (int o = 256; o; o >>= 1) { if (tid < o) sh[tid] += sh[tid + o]; __syncthreads(); }
    if (tid == 0) out[0] = sh[0] / (float)GG;
}

__global__ void transpose_kernel(const float* __restrict__ henv, float* __restrict__ henvT) {
    int idx = blockIdx.x * blockDim.x + threadIdx.x;
    if (idx >= GG * EMB) return;
    int g = idx / EMB, d = idx % EMB;
    henvT[d * GG + g] = henv[idx];
}

__global__ void rowsum_kernel(const float* __restrict__ S, const float* __restrict__ na,
                              const float* __restrict__ nc, float* __restrict__ rowsum) {
    int g = blockIdx.x, tid = threadIdx.x;
    float nag = na[g];
    float local = 0.f;
    for (int j = tid; j < GG; j += 256) {
        float denom = nag * nc[j] + 1e-8f;
        local += expf(S[(size_t)g * GG + j] / denom * INV_T);
    }
    __shared__ float sh[256];
    sh[tid] = local; __syncthreads();
    for (int o = 128; o; o >>= 1) { if (tid < o) sh[tid] += sh[tid + o]; __syncthreads(); }
    if (tid == 0) rowsum[g] = sh[0];
}

__global__ void losscon_kernel(const float* __restrict__ posdot, const float* __restrict__ na,
                               const float* __restrict__ nb, const float* __restrict__ rowsum,
                               float* __restrict__ out) {
    int tid = threadIdx.x;
    float local = 0.f;
    for (int g = tid; g < GG; g += 512) {
        float pos = expf(posdot[g] / (na[g] * nb[g] + 1e-8f) * INV_T);
        local += -logf(pos / (rowsum[g] + pos));
    }
    __shared__ float sh[512];
    sh[tid] = local; __syncthreads();
    for (int o = 256; o; o >>= 1) { if (tid < o) sh[tid] += sh[tid + o]; __syncthreads(); }
    if (tid == 0) out[0] = sh[0] / (float)GG;
}

__global__ void hin_kernel(const float* __restrict__ hr, const float* __restrict__ henv,
                           const int* __restrict__ perm, float* __restrict__ hin) {
    int idx = blockIdx.x * blockDim.x + threadIdx.x;
    if (idx >= GG * EMB) return;
    int g = idx / EMB, d = idx % EMB;
    float r = hr[idx];
    hin[idx] = r + henv[(size_t)perm[g] * EMB + d];
    hin[(size_t)(GG + g) * EMB + d] = r;
}

__global__ void pred2_kernel(const float* __restrict__ tmp, const float* __restrict__ Wp2,
                             const float* __restrict__ bp2, float* __restrict__ out) {
    int idx = blockIdx.x * blockDim.x + threadIdx.x;
    if (idx >= 2 * GG * TASKS) return;
    int row = idx / TASKS, t = idx % TASKS;
    const float* r = tmp + (size_t)row * EMB2;
    float acc = bp2[t];
    for (int k = 0; k < EMB2; k++) acc = fmaf(r[k], Wp2[k * TASKS + t], acc);
    int o = (row < GG) ? (row * TASKS + t) : (GG * TASKS + (row - GG) * TASKS + t);
    out[o] = acc;
}

// =====================================================================================
extern "C" void kernel_launch(void* const* d_in, const int* in_sizes, int n_in,
                              void* d_out, int out_size) {
    const float* x         = (const float*)d_in[0];
    const float* edge_attr = (const float*)d_in[1];
    const int*   edge_index= (const int*)  d_in[2];
    const int*   batch     = (const int*)  d_in[3];
    const float* gumbel    = (const float*)d_in[4];
    const int*   perm      = (const int*)  d_in[5];
    const float* W_enc = (const float*)d_in[6];
    const float* b_enc = (const float*)d_in[7];
    const float* We_g  = (const float*)d_in[8];
    const float* be_g  = (const float*)d_in[9];
    const float* W1_g  = (const float*)d_in[10];
    const float* b1_g  = (const float*)d_in[11];
    const float* W2_g  = (const float*)d_in[12];
    const float* b2_g  = (const float*)d_in[13];
    const float* We_r  = (const float*)d_in[14];
    const float* be_r  = (const float*)d_in[15];
    const float* W1_r  = (const float*)d_in[16];
    const float* b1_r  = (const float*)d_in[17];
    const float* W2_r  = (const float*)d_in[18];
    const float* b2_r  = (const float*)d_in[19];
    const float* Wg1   = (const float*)d_in[20];
    const float* bg1   = (const float*)d_in[21];
    const float* Wg2   = (const float*)d_in[22];
    const float* bg2   = (const float*)d_in[23];
    const float* Wp1   = (const float*)d_in[24];
    const float* bp1   = (const float*)d_in[25];
    const float* Wp2   = (const float*)d_in[26];
    const float* bp2   = (const float*)d_in[27];
    float* out = (float*)d_out;

    const int* src = edge_index;
    const int* dst = edge_index + EE;

    float *xfeat, *hb, *xr, *agg, *tmp, *gate, *hr, *henv, *hout, *henvT, *S;
    float *na, *nb, *nc, *posdot, *rnum, *envnum, *rowsum, *hin;
    __nv_bfloat16 *AS, *tmpS, *WS1, *WS2;
    cudaGetSymbolAddress((void**)&xfeat, d_xfeat);
    cudaGetSymbolAddress((void**)&hb, d_hb);
    cudaGetSymbolAddress((void**)&xr, d_xr);
    cudaGetSymbolAddress((void**)&agg, d_agg);
    cudaGetSymbolAddress((void**)&tmp, d_tmp);
    cudaGetSymbolAddress((void**)&gate, d_gate);
    cudaGetSymbolAddress((void**)&hr, d_hr);
    cudaGetSymbolAddress((void**)&henv, d_henv);
    cudaGetSymbolAddress((void**)&hout, d_hout);
    cudaGetSymbolAddress((void**)&henvT, d_henvT);
    cudaGetSymbolAddress((void**)&S, d_S);
    cudaGetSymbolAddress((void**)&na, d_na);
    cudaGetSymbolAddress((void**)&nb, d_nb);
    cudaGetSymbolAddress((void**)&nc, d_nc);
    cudaGetSymbolAddress((void**)&posdot, d_posdot);
    cudaGetSymbolAddress((void**)&rnum, d_rnum);
    cudaGetSymbolAddress((void**)&envnum, d_envnum);
    cudaGetSymbolAddress((void**)&rowsum, d_rowsum);
    cudaGetSymbolAddress((void**)&hin, d_hin);
    cudaGetSymbolAddress((void**)&AS, d_AS);
    cudaGetSymbolAddress((void**)&tmpS, d_tmpS);
    cudaGetSymbolAddress((void**)&WS1, d_WS1all);
    cudaGetSymbolAddress((void**)&WS2, d_WS2all);

    cudaFuncSetAttribute(hgemm, cudaFuncAttributeMaxDynamicSharedMemorySize, HG_SMEM);

    const size_t rowBytes = (size_t)NN * EMB * sizeof(float);
    const size_t ws1slice = (size_t)KP3 * NPAD1;
    const size_t ws2slice = (size_t)KP6 * NPAD2;

    // prologue: encoder + all weight splits (no inter-deps)
    enc_kernel<<<(NN * EMB + 255) / 256, 256>>>(x, W_enc, b_enc, xfeat);
    cudaMemcpyAsync(hb, xfeat, rowBytes, cudaMemcpyDeviceToDevice);
    cudaMemcpyAsync(xr, xfeat, rowBytes, cudaMemcpyDeviceToDevice);
    {
        dim3 g1((900 * NPAD1 + 255) / 256, 9);
        splitW1_all<<<g1, 256>>>(W1_g, W1_r, Wg1, Wp1, WS1);
        dim3 g2((1800 * NPAD2 + 255) / 256, 7);
        splitW2_all<<<g2, 256>>>(W2_g, W2_r, WS2);
    }

    const int edgeBlocks = (EE + 7) / 8;
    const int MT = (NN + 127) / 128;
    dim3 gridG1(NPAD1 / 128, MT);   // 5 x 235
    dim3 gridG2(NPAD2 / 128, MT);   // 3 x 235
    const int splitABlk = (NN * (EMB / 4) + 255) / 256;

    // enc GIN stack (L=5)
    for (int l = 0; l < 5; l++) {
        cudaMemsetAsync(agg, 0, rowBytes);
        edge_mp<<<edgeBlocks, 256>>>(hb, agg, src, dst, edge_attr,
                                     We_g + l * 3 * EMB, be_g + l * EMB);
        splitAB_kernel<<<splitABlk, 256>>>(agg, hb, NN, AS);
        hgemm<<<gridG1, 256, HG_SMEM>>>(AS, KP3, WS1 + l * ws1slice, NPAD1, b1_g + l * EMB2,
                                        nullptr, nullptr, tmpS, KP6, NN, 600, KP3, 4);
        hgemm<<<gridG2, 256, HG_SMEM>>>(tmpS, KP6, WS2 + l * ws2slice, NPAD2, b2_g + l * EMB,
                                        hb, hb, nullptr, 0, NN, 300, KP6, (l < 4) ? 1 : 2);
    }
    // rat GIN stack (L=2); last layer also emits split of xr for the gate GEMM
    for (int l = 0; l < 2; l++) {
        cudaMemsetAsync(agg, 0, rowBytes);
        edge_mp<<<edgeBlocks, 256>>>(xr, agg, src, dst, edge_attr,
                                     We_r + l * 3 * EMB, be_r + l * EMB);
        splitAB_kernel<<<splitABlk, 256>>>(agg, xr, NN, AS);
        hgemm<<<gridG1, 256, HG_SMEM>>>(AS, KP3, WS1 + (5 + l) * ws1slice, NPAD1, b1_r + l * EMB2,
                                        nullptr, nullptr, tmpS, KP6, NN, 600, KP3, 4);
        hgemm<<<gridG2, 256, HG_SMEM>>>(tmpS, KP6, WS2 + (5 + l) * ws2slice, NPAD2,
                                        b2_r + l * EMB, xr, xr, (l == 1) ? AS : nullptr,
                                        KP3, NN, 300, KP6, (l < 1) ? 1 : 5);
    }

    // gate: tmp = relu(xr @ Wg1 + bg1); AS already holds split(xr)
    hgemm<<<gridG1, 256, HG_SMEM>>>(AS, KP3, WS1 + 7 * ws1slice, NPAD1, bg1,
                                    tmp, nullptr, nullptr, 0, NN, 600, KP3, 0);
    gate_kernel<<<(NN * 32 + 255) / 256, 256>>>(tmp, Wg2, bg2, gumbel, gate);

    // per-graph reductions
    segment_kernel<<<GG, 512>>>(hb, gate, batch, hr, henv, hout, rnum, envnum);
    norm_kernel<<<GG, 128>>>(hr, henv, hout, na, nb, nc, posdot);
    lossreg_kernel<<<1, 512>>>(rnum, envnum, out + 2 * GG * TASKS);

    // contrastive loss: S = hr @ henv^T (fp32: feeds exp(5*cos))
    transpose_kernel<<<(GG * EMB + 255) / 256, 256>>>(henv, henvT);
    dim3 gridS((GG + BN - 1) / BN, (GG + BM - 1) / BM);
    sgemm_opt<<<gridS, 256>>>(hr, henvT, S, GG, GG, EMB);
    rowsum_kernel<<<GG, 256>>>(S, na, nc, rowsum);
    losscon_kernel<<<1, 512>>>(posdot, na, nb, rowsum, out + 2 * GG * TASKS + 1);

    // prediction MLPs
    hin_kernel<<<(GG * EMB + 255) / 256, 256>>>(hr, henv, perm, hin);
    splitAB_kernel<<<(2 * GG * (EMB / 4) + 255) / 256, 256>>>(hin, nullptr, 2 * GG, AS);
    dim3 gridP(NPAD1 / 128, (2 * GG + 127) / 128);
    hgemm<<<gridP, 256, HG_SMEM>>>(AS, KP3, WS1 + 8 * ws1slice, NPAD1, bp1,
                                   tmp, nullptr, nullptr, 0, 2 * GG, 600, KP3, 0);
    pred2_kernel<<<(2 * GG * TASKS + 127) / 128, 128>>>(tmp, Wp2, bp2, out);
}

// round 13
// speedup vs baseline: 1.1409x; 1.1409x over previous
#include <cuda_runtime.h>
#include <cuda_bf16.h>
#include <math.h>
#include <stdint.h>

#define NN 30000
#define EE 240000
#define GG 1500
#define EMB 300
#define EMB2 600
#define TASKS 12
#define GAMMA 0.4f
#define INV_T 5.0f   // 1 / T_CON

#define KP3 928      // padded 3*300 (29 K-stages of 32)
#define KP6 1824     // padded 3*600 (57 K-stages of 32)
#define NPAD1 640    // padded N=600
#define NPAD2 384    // padded N=300

// ---------------- scratch (static device allocations; zero-initialized) ----------------
__device__ float d_xfeat[NN * EMB];
__device__ float d_hb[NN * EMB];
__device__ float d_xr[NN * EMB];
__device__ float d_agg[NN * EMB];
__device__ float d_tmp[NN * EMB2];
__device__ float d_gate[NN];
__device__ float d_hr[GG * EMB];
__device__ float d_henv[GG * EMB];
__device__ float d_hout[GG * EMB];
__device__ float d_henvT[EMB * GG];
__device__ float d_S[GG * GG];
__device__ float d_na[GG], d_nb[GG], d_nc[GG], d_posdot[GG];
__device__ float d_rnum[GG], d_envnum[GG];
__device__ float d_rowsum[GG];
__device__ float d_hin[2 * GG * EMB];
__device__ __nv_bfloat16 d_AS[(size_t)NN * KP3];
__device__ __nv_bfloat16 d_tmpS[(size_t)NN * KP6];
__device__ __nv_bfloat16 d_WS1all[(size_t)9 * KP3 * NPAD1];
__device__ __nv_bfloat16 d_WS2all[(size_t)7 * KP6 * NPAD2];

__device__ __forceinline__ uint32_t pack_bf2(__nv_bfloat16 lo, __nv_bfloat16 hi) {
    return ((uint32_t)__bfloat16_as_ushort(hi) << 16) | (uint32_t)__bfloat16_as_ushort(lo);
}

// ---------------- node encoder ----------------
__global__ void enc_kernel(const float* __restrict__ x, const float* __restrict__ W,
                           const float* __restrict__ b, float* __restrict__ out) {
    int idx = blockIdx.x * blockDim.x + threadIdx.x;
    if (idx >= NN * EMB) return;
    int i = idx / EMB, j = idx % EMB;
    const float* xr = x + i * 9;
    float acc = b[j];
#pragma unroll
    for (int k = 0; k < 9; k++) acc += xr[k] * W[k * EMB + j];
    out[idx] = acc;
}

// ------------- edge message passing: float4 loads + float4 vector atomics -------------
__global__ void edge_mp(const float* __restrict__ x, float* __restrict__ agg,
                        const int* __restrict__ src, const int* __restrict__ dst,
                        const float* __restrict__ ea, const float* __restrict__ We,
                        const float* __restrict__ be) {
    int w = (blockIdx.x * blockDim.x + threadIdx.x) >> 5;
    int lane = threadIdx.x & 31;
    if (w >= EE) return;
    int s = src[w], d = dst[w];
    float a0 = ea[w * 3 + 0], a1 = ea[w * 3 + 1], a2 = ea[w * 3 + 2];
    const float4* xs4 = (const float4*)(x + (size_t)s * EMB);
    const float4* We0 = (const float4*)We;
    const float4* We1 = (const float4*)(We + EMB);
    const float4* We2 = (const float4*)(We + 2 * EMB);
    const float4* be4 = (const float4*)be;
    float4* ag4 = (float4*)(agg + (size_t)d * EMB);
    for (int k4 = lane; k4 < EMB / 4; k4 += 32) {
        float4 xv = xs4[k4];
        float4 w0 = We0[k4], w1 = We1[k4], w2 = We2[k4], bb = be4[k4];
        float4 m;
        m.x = fmaxf(xv.x + fmaf(a0, w0.x, fmaf(a1, w1.x, fmaf(a2, w2.x, bb.x))), 0.f);
        m.y = fmaxf(xv.y + fmaf(a0, w0.y, fmaf(a1, w1.y, fmaf(a2, w2.y, bb.y))), 0.f);
        m.z = fmaxf(xv.z + fmaf(a0, w0.z, fmaf(a1, w1.z, fmaf(a2, w2.z, bb.z))), 0.f);
        m.w = fmaxf(xv.w + fmaf(a0, w0.w, fmaf(a1, w1.w, fmaf(a2, w2.w, bb.w))), 0.f);
        atomicAdd(&ag4[k4], m);   // sm_90+ vector red.global.add.v4.f32
    }
}

// ---------------- splits (float4 / uint2) ----------------
__global__ void splitAB_kernel(const float* __restrict__ in, const float* __restrict__ base,
                               int M, __nv_bfloat16* __restrict__ out) {
    int idx = blockIdx.x * blockDim.x + threadIdx.x;
    if (idx >= M * (EMB / 4)) return;
    int m = idx / (EMB / 4), q4 = idx % (EMB / 4);
    float4 v = ((const float4*)(in))[(size_t)m * (EMB / 4) + q4];
    if (base) {
        float4 b = ((const float4*)(base))[(size_t)m * (EMB / 4) + q4];
        v.x += b.x; v.y += b.y; v.z += b.z; v.w += b.w;
    }
    float vv[4] = {v.x, v.y, v.z, v.w};
    __nv_bfloat16 h[4], l[4];
#pragma unroll
    for (int i = 0; i < 4; i++) {
        h[i] = __float2bfloat16(vv[i]);
        l[i] = __float2bfloat16(vv[i] - __bfloat162float(h[i]));
    }
    uint2 H, L;
    H.x = pack_bf2(h[0], h[1]); H.y = pack_bf2(h[2], h[3]);
    L.x = pack_bf2(l[0], l[1]); L.y = pack_bf2(l[2], l[3]);
    __nv_bfloat16* row = out + (size_t)m * KP3;
    int c = q4 * 4;
    *(uint2*)(row + c) = H;
    *(uint2*)(row + 300 + c) = L;
    *(uint2*)(row + 600 + c) = H;
}

// batched weight splits. B' rows [h; h; l] (3K), cols padded Npad.
__global__ void splitW1_all(const float* __restrict__ W1g, const float* __restrict__ W1r,
                            const float* __restrict__ Wg1, const float* __restrict__ Wp1,
                            __nv_bfloat16* __restrict__ WS) {
    int mat = blockIdx.y;
    const float* W = (mat < 5) ? (W1g + (size_t)mat * 300 * 600)
                   : (mat < 7) ? (W1r + (size_t)(mat - 5) * 300 * 600)
                   : (mat == 7) ? Wg1 : Wp1;
    __nv_bfloat16* dst = WS + (size_t)mat * KP3 * NPAD1;
    int idx = blockIdx.x * blockDim.x + threadIdx.x;
    if (idx >= 900 * NPAD1) return;
    int k3 = idx / NPAD1, n = idx % NPAD1;
    __nv_bfloat16 r = __float2bfloat16(0.f);
    if (n < 600) {
        int seg = k3 / 300, k = k3 % 300;
        float v = W[(size_t)k * 600 + n];
        __nv_bfloat16 h = __float2bfloat16(v);
        r = (seg < 2) ? h : __float2bfloat16(v - __bfloat162float(h));
    }
    dst[(size_t)k3 * NPAD1 + n] = r;
}
__global__ void splitW2_all(const float* __restrict__ W2g, const float* __restrict__ W2r,
                            __nv_bfloat16* __restrict__ WS) {
    int mat = blockIdx.y;
    const float* W = (mat < 5) ? (W2g + (size_t)mat * 600 * 300)
                               : (W2r + (size_t)(mat - 5) * 600 * 300);
    __nv_bfloat16* dst = WS + (size_t)mat * KP6 * NPAD2;
    int idx = blockIdx.x * blockDim.x + threadIdx.x;
    if (idx >= 1800 * NPAD2) return;
    int k3 = idx / NPAD2, n = idx % NPAD2;
    __nv_bfloat16 r = __float2bfloat16(0.f);
    if (n < 300) {
        int seg = k3 / 600, k = k3 % 600;
        float v = W[(size_t)k * 300 + n];
        __nv_bfloat16 h = __float2bfloat16(v);
        r = (seg < 2) ? h : __float2bfloat16(v - __bfloat162float(h));
    }
    dst[(size_t)k3 * NPAD2 + n] = r;
}

// ---------------- epilogue flags ----------------
// ep: 0 = +bias,relu ; 1 = +bias,relu,+resid ; 2 = +bias,+resid ;
//     4 = +bias,relu -> split only ; 5 = +bias,+resid -> C AND split
__device__ __forceinline__ void epilogue_elem(int ep, float v, int r, int c, int N,
                                              const float* resid, float* C,
                                              __nv_bfloat16* outS, int ldS) {
    if (ep == 0 || ep == 1 || ep == 4) v = fmaxf(v, 0.f);
    if (ep == 1 || ep == 2 || ep == 5) v += resid[(size_t)r * N + c];
    if (ep == 4 || ep == 5) {
        __nv_bfloat16 h = __float2bfloat16(v);
        __nv_bfloat16 l = __float2bfloat16(v - __bfloat162float(h));
        __nv_bfloat16* rowS = outS + (size_t)r * ldS;
        rowS[c] = h; rowS[N + c] = l; rowS[2 * N + c] = h;
    }
    if (ep != 4) C[(size_t)r * N + c] = v;
}

// ============================================================================
// bf16 HMMA GEMM, 3-stage cp.async ring. Tile 128x128, 8 warps. (R8 config)
// ============================================================================
#define HA_STR 40
#define HB_STR 136
#define HA_BYTES (128 * HA_STR * 2)
#define HSTAGE_BYTES (HA_BYTES + 32 * HB_STR * 2)
#define HG_SMEM (3 * HSTAGE_BYTES)

__global__ __launch_bounds__(256, 2)
void hgemm(const __nv_bfloat16* __restrict__ A, int lda,
           const __nv_bfloat16* __restrict__ B, int ldb,
           const float* __restrict__ bias, float* __restrict__ C,
           const float* __restrict__ resid,
           __nv_bfloat16* __restrict__ outS, int ldS,
           int M, int N, int K3, int ep) {
    extern __shared__ char hsm[];
    const int tid = threadIdx.x;
    const int wid = tid >> 5, lane = tid & 31;
    const int grp = lane >> 2, tig = lane & 3;
    const int wm = (wid >> 2) * 64, wn = (wid & 3) * 32;
    const int lrow = lane & 15, lcol = (lane >> 4) * 8;
    const int row0 = blockIdx.y * 128;
    const int col0 = blockIdx.x * 128;
    const int nk = K3 / 32;

    auto loadTile = [&](int t) {
        char* stA = hsm + (t % 3) * HSTAGE_BYTES;
        char* stB = stA + HA_BYTES;
        const int kb = t * 32;
#pragma unroll
        for (int i = 0; i < 2; i++) {
            int c = tid * 2 + i;
            int ar = c >> 2, ak = (c & 3) * 8;
            int gr = row0 + ar;
            const __nv_bfloat16* gp = A + (size_t)(gr < M ? gr : M - 1) * lda + kb + ak;
            uint32_t sp = (uint32_t)__cvta_generic_to_shared(stA + (ar * HA_STR + ak) * 2);
            int sz = (gr < M) ? 16 : 0;
            asm volatile("cp.async.cg.shared.global [%0], [%1], 16, %2;"
                         :: "r"(sp), "l"(gp), "r"(sz) : "memory");
        }
#pragma unroll
        for (int i = 0; i < 2; i++) {
            int c = tid * 2 + i;
            int br = c >> 4, bn = (c & 15) * 8;
            const __nv_bfloat16* gp = B + (size_t)(kb + br) * ldb + col0 + bn;
            uint32_t sp = (uint32_t)__cvta_generic_to_shared(stB + (br * HB_STR + bn) * 2);
            asm volatile("cp.async.cg.shared.global [%0], [%1], 16, 16;"
                         :: "r"(sp), "l"(gp) : "memory");
        }
        asm volatile("cp.async.commit_group;" ::: "memory");
    };

    float acc[4][4][4];
#pragma unroll
    for (int i = 0; i < 4; i++)
#pragma unroll
        for (int j = 0; j < 4; j++)
#pragma unroll
            for (int q = 0; q < 4; q++) acc[i][j][q] = 0.f;

    loadTile(0);
    if (nk > 1) loadTile(1);

    for (int t = 0; t < nk; t++) {
        if (t + 1 < nk)
            asm volatile("cp.async.wait_group 1;" ::: "memory");
        else
            asm volatile("cp.async.wait_group 0;" ::: "memory");
        __syncthreads();
        if (t + 2 < nk) loadTile(t + 2);

        char* stA = hsm + (t % 3) * HSTAGE_BYTES;
        __nv_bfloat16* Asm = (__nv_bfloat16*)stA;
        __nv_bfloat16* Bsm = (__nv_bfloat16*)(stA + HA_BYTES);
#pragma unroll
        for (int ks = 0; ks < 2; ks++) {
            const int k0 = ks * 16;
            uint32_t af[4][4], bf[4][2];
#pragma unroll
            for (int mt = 0; mt < 4; mt++) {
                uint32_t sa = (uint32_t)__cvta_generic_to_shared(
                    &Asm[(wm + mt * 16 + lrow) * HA_STR + k0 + lcol]);
                asm volatile(
                    "ldmatrix.sync.aligned.m8n8.x4.shared.b16 {%0,%1,%2,%3}, [%4];"
                    : "=r"(af[mt][0]), "=r"(af[mt][1]), "=r"(af[mt][2]), "=r"(af[mt][3])
                    : "r"(sa));
            }
#pragma unroll
            for (int ng = 0; ng < 2; ng++) {
                uint32_t sb = (uint32_t)__cvta_generic_to_shared(
                    &Bsm[(k0 + lrow) * HB_STR + wn + ng * 16 + lcol]);
                uint32_t r0, r1, r2, r3;
                asm volatile(
                    "ldmatrix.sync.aligned.m8n8.x4.trans.shared.b16 {%0,%1,%2,%3}, [%4];"
                    : "=r"(r0), "=r"(r1), "=r"(r2), "=r"(r3) : "r"(sb));
                bf[ng * 2][0] = r0; bf[ng * 2][1] = r1;
                bf[ng * 2 + 1][0] = r2; bf[ng * 2 + 1][1] = r3;
            }
#pragma unroll
            for (int mt = 0; mt < 4; mt++)
#pragma unroll
                for (int nt = 0; nt < 4; nt++)
                    asm volatile(
                        "mma.sync.aligned.m16n8k16.row.col.f32.bf16.bf16.f32 "
                        "{%0,%1,%2,%3}, {%4,%5,%6,%7}, {%8,%9}, {%0,%1,%2,%3};"
                        : "+f"(acc[mt][nt][0]), "+f"(acc[mt][nt][1]),
                          "+f"(acc[mt][nt][2]), "+f"(acc[mt][nt][3])
                        : "r"(af[mt][0]), "r"(af[mt][1]), "r"(af[mt][2]), "r"(af[mt][3]),
                          "r"(bf[nt][0]), "r"(bf[nt][1]));
        }
    }

#pragma unroll
    for (int mt = 0; mt < 4; mt++)
#pragma unroll
        for (int nt = 0; nt < 4; nt++) {
            int rA = row0 + wm + mt * 16 + grp;
            int cA = col0 + wn + nt * 8 + 2 * tig;
#pragma unroll
            for (int half = 0; half < 2; half++) {
                int r = rA + half * 8;
                if (r >= M) continue;
#pragma unroll
                for (int q = 0; q < 2; q++) {
                    int c = cA + q;
                    if (c >= N) continue;
                    epilogue_elem(ep, acc[mt][nt][half * 2 + q] + bias[c],
                                  r, c, N, resid, C, outS, ldS);
                }
            }
        }
}

// ---------------- fp32 SGEMM (S matrix only) ----------------
#define BM 128
#define BN 128
#define BK 16
__global__ __launch_bounds__(256, 2)
void sgemm_opt(const float* __restrict__ A, const float* __restrict__ B,
               float* __restrict__ C, int M, int N, int K) {
    __shared__ float As[2][BK][BM + 4];
    __shared__ float Bs[2][BK][BN];
    const int tid = threadIdx.x;
    const int row0 = blockIdx.y * BM;
    const int col0 = blockIdx.x * BN;
    const int tx = tid & 15, ty = tid >> 4;
    const int ar = tid >> 1, ak0 = (tid & 1) * 8;
    const int br = tid >> 5, bc = (tid & 31) * 4;
    float4 aReg[2], bReg[2];
    const int gr = row0 + ar;
    const bool arow_ok = (gr < M);
    const float* Arow = A + (size_t)gr * K;

    auto loadA = [&](int k0) {
#pragma unroll
        for (int v = 0; v < 2; v++) {
            int k = k0 + ak0 + v * 4;
            float4 t = make_float4(0.f, 0.f, 0.f, 0.f);
            if (arow_ok) {
                if (k + 3 < K) t = *(const float4*)(Arow + k);
                else {
                    float u[4] = {0.f, 0.f, 0.f, 0.f};
#pragma unroll
                    for (int q = 0; q < 4; q++) if (k + q < K) u[q] = Arow[k + q];
                    t = make_float4(u[0], u[1], u[2], u[3]);
                }
            }
            aReg[v] = t;
        }
    };
    auto loadB = [&](int k0) {
#pragma unroll
        for (int v = 0; v < 2; v++) {
            int k = k0 + br + v * 8;
            int c = col0 + bc;
            float4 t = make_float4(0.f, 0.f, 0.f, 0.f);
            if (k < K) {
                const float* Brow = B + (size_t)k * N;
                if (c + 3 < N) t = *(const float4*)(Brow + c);
                else {
                    float u[4] = {0.f, 0.f, 0.f, 0.f};
#pragma unroll
                    for (int q = 0; q < 4; q++) if (c + q < N) u[q] = Brow[c + q];
                    t = make_float4(u[0], u[1], u[2], u[3]);
                }
            }
            bReg[v] = t;
        }
    };
    auto storeAB = [&](int buf) {
#pragma unroll
        for (int v = 0; v < 2; v++) {
            As[buf][ak0 + v * 4 + 0][ar] = aReg[v].x;
            As[buf][ak0 + v * 4 + 1][ar] = aReg[v].y;
            As[buf][ak0 + v * 4 + 2][ar] = aReg[v].z;
            As[buf][ak0 + v * 4 + 3][ar] = aReg[v].w;
            *(float4*)&Bs[buf][br + v * 8][bc] = bReg[v];
        }
    };

    float acc[8][8] = {};
    const int nk = (K + BK - 1) / BK;
    loadA(0); loadB(0); storeAB(0);
    __syncthreads();
    for (int t = 0; t < nk; t++) {
        const int buf = t & 1;
        if (t + 1 < nk) { loadA((t + 1) * BK); loadB((t + 1) * BK); }
#pragma unroll
        for (int kk = 0; kk < BK; kk++) {
            float a[8], b[8];
            *(float4*)&a[0] = *(const float4*)&As[buf][kk][ty * 8];
            *(float4*)&a[4] = *(const float4*)&As[buf][kk][ty * 8 + 4];
            *(float4*)&b[0] = *(const float4*)&Bs[buf][kk][tx * 8];
            *(float4*)&b[4] = *(const float4*)&Bs[buf][kk][tx * 8 + 4];
#pragma unroll
            for (int i = 0; i < 8; i++)
#pragma unroll
                for (int j = 0; j < 8; j++) acc[i][j] = fmaf(a[i], b[j], acc[i][j]);
        }
        if (t + 1 < nk) { storeAB(buf ^ 1); __syncthreads(); }
    }
#pragma unroll
    for (int i = 0; i < 8; i++) {
        int r = row0 + ty * 8 + i;
        if (r >= M) continue;
#pragma unroll
        for (int j = 0; j < 8; j++) {
            int c = col0 + tx * 8 + j;
            if (c >= N) continue;
            C[(size_t)r * N + c] = acc[i][j];
        }
    }
}

// ---------------- gate ----------------
__global__ void gate_kernel(const float* __restrict__ tmp, const float* __restrict__ Wg2,
                            const float* __restrict__ bg2, const float* __restrict__ gumbel,
                            float* __restrict__ gate) {
    int w = (blockIdx.x * blockDim.x + threadIdx.x) >> 5;
    int lane = threadIdx.x & 31;
    if (w >= NN) return;
    const float* row = tmp + (size_t)w * EMB2;
    float a0 = 0.f, a1 = 0.f;
    for (int k = lane; k < EMB2; k += 32) {
        float v = row[k];
        a0 = fmaf(v, Wg2[2 * k + 0], a0);
        a1 = fmaf(v, Wg2[2 * k + 1], a1);
    }
    for (int o = 16; o; o >>= 1) {
        a0 += __shfl_down_sync(0xffffffffu, a0, o);
        a1 += __shfl_down_sync(0xffffffffu, a1, o);
    }
    if (lane == 0) {
        float z0 = a0 + bg2[0] + gumbel[2 * w + 0];
        float z1 = a1 + bg2[1] + gumbel[2 * w + 1];
        gate[w] = 1.f / (1.f + expf(z0 - z1));
    }
}

// ---------------- per-graph segment means (batch sorted) ----------------
__device__ __forceinline__ int lower_bound_batch(const int* __restrict__ batch, int val) {
    int lo = 0, hi = NN;
    while (lo < hi) {
        int mid = (lo + hi) >> 1;
        if (batch[mid] < val) lo = mid + 1; else hi = mid;
    }
    return lo;
}

__global__ void segment_kernel(const float* __restrict__ hb, const float* __restrict__ gate,
                               const int* __restrict__ batch,
                               float* __restrict__ hr, float* __restrict__ henv,
                               float* __restrict__ hout, float* __restrict__ rnum,
                               float* __restrict__ envnum) {
    int g = blockIdx.x;
    int s = lower_bound_batch(batch, g);
    int e = lower_bound_batch(batch, g + 1);
    float cnt = fmaxf((float)(e - s), 1.f);
    int tid = threadIdx.x;
    if (tid < EMB) {
        float ar = 0.f, ae = 0.f, ao = 0.f;
        for (int n = s; n < e; n++) {
            float h = hb[(size_t)n * EMB + tid];
            float gt = gate[n];
            ar = fmaf(gt, h, ar);
            ae = fmaf(1.f - gt, h, ae);
            ao += h;
        }
        hr[g * EMB + tid] = ar / cnt;
        henv[g * EMB + tid] = ae / cnt;
        hout[g * EMB + tid] = ao / cnt;
    }
    __shared__ float sh[512];
    float gs = 0.f;
    for (int n = s + tid; n < e; n += blockDim.x) gs += gate[n];
    sh[tid] = gs;
    __syncthreads();
    for (int o = 256; o; o >>= 1) {
        if (tid < o) sh[tid] += sh[tid + o];
        __syncthreads();
    }
    if (tid == 0) {
        rnum[g] = sh[0] + 1e-8f;
        envnum[g] = ((float)(e - s) - sh[0]) + 1e-8f;
    }
}

__global__ void norm_kernel(const float* __restrict__ hr, const float* __restrict__ henv,
                            const float* __restrict__ hout, float* __restrict__ na,
                            float* __restrict__ nb, float* __restrict__ nc,
                            float* __restrict__ posdot) {
    int g = blockIdx.x, tid = threadIdx.x;
    float s1 = 0, s2 = 0, s3 = 0, s4 = 0;
    for (int d = tid; d < EMB; d += 128) {
        float a = hr[g * EMB + d], o = hout[g * EMB + d], ev = henv[g * EMB + d];
        s1 = fmaf(a, a, s1); s2 = fmaf(o, o, s2); s3 = fmaf(ev, ev, s3); s4 = fmaf(a, o, s4);
    }
    __shared__ float sh[128];
    auto red = [&](float v) -> float {
        sh[tid] = v; __syncthreads();
        for (int o = 64; o; o >>= 1) { if (tid < o) sh[tid] += sh[tid + o]; __syncthreads(); }
        float r = sh[0]; __syncthreads();
        return r;
    };
    float r1 = red(s1), r2 = red(s2), r3 = red(s3), r4 = red(s4);
    if (tid == 0) {
        na[g] = sqrtf(r1); nb[g] = sqrtf(r2); nc[g] = sqrtf(r3); posdot[g] = r4;
    }
}

__global__ void lossreg_kernel(const float* __restrict__ rnum, const float* __restrict__ envnum,
                               float* __restrict__ out) {
    int tid = threadIdx.x;
    float local = 0.f;
    for (int g = tid; g < GG; g += 512) {
        float r = rnum[g], ev = envnum[g];
        local += fabsf(r / (r + ev) - GAMMA);
    }
    __shared__ float sh[512];
    sh[tid] = local; __syncthreads();
    for (int o = 256; o; o >>= 1) { if (tid < o) sh[tid] += sh[tid + o]; __syncthreads(); }
    if (tid == 0) out[0] = sh[0] / (float)GG;
}

__global__ void transpose_kernel(const float* __restrict__ henv, float* __restrict__ henvT) {
    int idx = blockIdx.x * blockDim.x + threadIdx.x;
    if (idx >= GG * EMB) return;
    int g = idx / EMB, d = idx % EMB;
    henvT[d * GG + g] = henv[idx];
}

__global__ void rowsum_kernel(const float* __restrict__ S, const float* __restrict__ na,
                              const float* __restrict__ nc, float* __restrict__ rowsum) {
    int g = blockIdx.x, tid = threadIdx.x;
    float nag = na[g];
    float local = 0.f;
    for (int j = tid; j < GG; j += 256) {
        float denom = nag * nc[j] + 1e-8f;
        local += expf(S[(size_t)g * GG + j] / denom * INV_T);
    }
    __shared__ float sh[256];
    sh[tid] = local; __syncthreads();
    for (int o = 128; o; o >>= 1) { if (tid < o) sh[tid] += sh[tid + o]; __syncthreads(); }
    if (tid == 0) rowsum[g] = sh[0];
}

__global__ void losscon_kernel(const float* __restrict__ posdot, const float* __restrict__ na,
                               const float* __restrict__ nb, const float* __restrict__ rowsum,
                               float* __restrict__ out) {
    int tid = threadIdx.x;
    float local = 0.f;
    for (int g = tid; g < GG; g += 512) {
        float pos = expf(posdot[g] / (na[g] * nb[g] + 1e-8f) * INV_T);
        local += -logf(pos / (rowsum[g] + pos));
    }
    __shared__ float sh[512];
    sh[tid] = local; __syncthreads();
    for (int o = 256; o; o >>= 1) { if (tid < o) sh[tid] += sh[tid + o]; __syncthreads(); }
    if (tid == 0) out[0] = sh[0] / (float)GG;
}

__global__ void hin_kernel(const float* __restrict__ hr, const float* __restrict__ henv,
                           const int* __restrict__ perm, float* __restrict__ hin) {
    int idx = blockIdx.x * blockDim.x + threadIdx.x;
    if (idx >= GG * EMB) return;
    int g = idx / EMB, d = idx % EMB;
    float r = hr[idx];
    hin[idx] = r + henv[(size_t)perm[g] * EMB + d];
    hin[(size_t)(GG + g) * EMB + d] = r;
}

__global__ void pred2_kernel(const float* __restrict__ tmp, const float* __restrict__ Wp2,
                             const float* __restrict__ bp2, float* __restrict__ out) {
    int idx = blockIdx.x * blockDim.x + threadIdx.x;
    if (idx >= 2 * GG * TASKS) return;
    int row = idx / TASKS, t = idx % TASKS;
    const float* r = tmp + (size_t)row * EMB2;
    float acc = bp2[t];
    for (int k = 0; k < EMB2; k++) acc = fmaf(r[k], Wp2[k * TASKS + t], acc);
    int o = (row < GG) ? (row * TASKS + t) : (GG * TASKS + (row - GG) * TASKS + t);
    out[o] = acc;
}

// =====================================================================================
extern "C" void kernel_launch(void* const* d_in, const int* in_sizes, int n_in,
                              void* d_out, int out_size) {
    const float* x         = (const float*)d_in[0];
    const float* edge_attr = (const float*)d_in[1];
    const int*   edge_index= (const int*)  d_in[2];
    const int*   batch     = (const int*)  d_in[3];
    const float* gumbel    = (const float*)d_in[4];
    const int*   perm      = (const int*)  d_in[5];
    const float* W_enc = (const float*)d_in[6];
    const float* b_enc = (const float*)d_in[7];
    const float* We_g  = (const float*)d_in[8];
    const float* be_g  = (const float*)d_in[9];
    const float* W1_g  = (const float*)d_in[10];
    const float* b1_g  = (const float*)d_in[11];
    const float* W2_g  = (const float*)d_in[12];
    const float* b2_g  = (const float*)d_in[13];
    const float* We_r  = (const float*)d_in[14];
    const float* be_r  = (const float*)d_in[15];
    const float* W1_r  = (const float*)d_in[16];
    const float* b1_r  = (const float*)d_in[17];
    const float* W2_r  = (const float*)d_in[18];
    const float* b2_r  = (const float*)d_in[19];
    const float* Wg1   = (const float*)d_in[20];
    const float* bg1   = (const float*)d_in[21];
    const float* Wg2   = (const float*)d_in[22];
    const float* bg2   = (const float*)d_in[23];
    const float* Wp1   = (const float*)d_in[24];
    const float* bp1   = (const float*)d_in[25];
    const float* Wp2   = (const float*)d_in[26];
    const float* bp2   = (const float*)d_in[27];
    float* out = (float*)d_out;

    const int* src = edge_index;
    const int* dst = edge_index + EE;

    float *xfeat, *hb, *xr, *agg, *tmp, *gate, *hr, *henv, *hout, *henvT, *S;
    float *na, *nb, *nc, *posdot, *rnum, *envnum, *rowsum, *hin;
    __nv_bfloat16 *AS, *tmpS, *WS1, *WS2;
    cudaGetSymbolAddress((void**)&xfeat, d_xfeat);
    cudaGetSymbolAddress((void**)&hb, d_hb);
    cudaGetSymbolAddress((void**)&xr, d_xr);
    cudaGetSymbolAddress((void**)&agg, d_agg);
    cudaGetSymbolAddress((void**)&tmp, d_tmp);
    cudaGetSymbolAddress((void**)&gate, d_gate);
    cudaGetSymbolAddress((void**)&hr, d_hr);
    cudaGetSymbolAddress((void**)&henv, d_henv);
    cudaGetSymbolAddress((void**)&hout, d_hout);
    cudaGetSymbolAddress((void**)&henvT, d_henvT);
    cudaGetSymbolAddress((void**)&S, d_S);
    cudaGetSymbolAddress((void**)&na, d_na);
    cudaGetSymbolAddress((void**)&nb, d_nb);
    cudaGetSymbolAddress((void**)&nc, d_nc);
    cudaGetSymbolAddress((void**)&posdot, d_posdot);
    cudaGetSymbolAddress((void**)&rnum, d_rnum);
    cudaGetSymbolAddress((void**)&envnum, d_envnum);
    cudaGetSymbolAddress((void**)&rowsum, d_rowsum);
    cudaGetSymbolAddress((void**)&hin, d_hin);
    cudaGetSymbolAddress((void**)&AS, d_AS);
    cudaGetSymbolAddress((void**)&tmpS, d_tmpS);
    cudaGetSymbolAddress((void**)&WS1, d_WS1all);
    cudaGetSymbolAddress((void**)&WS2, d_WS2all);

    cudaFuncSetAttribute(hgemm, cudaFuncAttributeMaxDynamicSharedMemorySize, HG_SMEM);

    const size_t rowBytes = (size_t)NN * EMB * sizeof(float);
    const size_t ws1slice = (size_t)KP3 * NPAD1;
    const size_t ws2slice = (size_t)KP6 * NPAD2;

    // prologue: encoder + all weight splits (no inter-deps)
    enc_kernel<<<(NN * EMB + 255) / 256, 256>>>(x, W_enc, b_enc, xfeat);
    cudaMemcpyAsync(hb, xfeat, rowBytes, cudaMemcpyDeviceToDevice);
    cudaMemcpyAsync(xr, xfeat, rowBytes, cudaMemcpyDeviceToDevice);
    {
        dim3 g1((900 * NPAD1 + 255) / 256, 9);
        splitW1_all<<<g1, 256>>>(W1_g, W1_r, Wg1, Wp1, WS1);
        dim3 g2((1800 * NPAD2 + 255) / 256, 7);
        splitW2_all<<<g2, 256>>>(W2_g, W2_r, WS2);
    }

    const int edgeBlocks = (EE + 7) / 8;
    const int MT = (NN + 127) / 128;
    dim3 gridG1(NPAD1 / 128, MT);   // 5 x 235
    dim3 gridG2(NPAD2 / 128, MT);   // 3 x 235
    const int splitABlk = (NN * (EMB / 4) + 255) / 256;

    // enc GIN stack (L=5)
    for (int l = 0; l < 5; l++) {
        cudaMemsetAsync(agg, 0, rowBytes);
        edge_mp<<<edgeBlocks, 256>>>(hb, agg, src, dst, edge_attr,
                                     We_g + l * 3 * EMB, be_g + l * EMB);
        splitAB_kernel<<<splitABlk, 256>>>(agg, hb, NN, AS);
        hgemm<<<gridG1, 256, HG_SMEM>>>(AS, KP3, WS1 + l * ws1slice, NPAD1, b1_g + l * EMB2,
                                        nullptr, nullptr, tmpS, KP6, NN, 600, KP3, 4);
        hgemm<<<gridG2, 256, HG_SMEM>>>(tmpS, KP6, WS2 + l * ws2slice, NPAD2, b2_g + l * EMB,
                                        hb, hb, nullptr, 0, NN, 300, KP6, (l < 4) ? 1 : 2);
    }
    // rat GIN stack (L=2); last layer also emits split of xr for the gate GEMM
    for (int l = 0; l < 2; l++) {
        cudaMemsetAsync(agg, 0, rowBytes);
        edge_mp<<<edgeBlocks, 256>>>(xr, agg, src, dst, edge_attr,
                                     We_r + l * 3 * EMB, be_r + l * EMB);
        splitAB_kernel<<<splitABlk, 256>>>(agg, xr, NN, AS);
        hgemm<<<gridG1, 256, HG_SMEM>>>(AS, KP3, WS1 + (5 + l) * ws1slice, NPAD1, b1_r + l * EMB2,
                                        nullptr, nullptr, tmpS, KP6, NN, 600, KP3, 4);
        hgemm<<<gridG2, 256, HG_SMEM>>>(tmpS, KP6, WS2 + (5 + l) * ws2slice, NPAD2,
                                        b2_r + l * EMB, xr, xr, (l == 1) ? AS : nullptr,
                                        KP3, NN, 300, KP6, (l < 1) ? 1 : 5);
    }

    // gate: tmp = relu(xr @ Wg1 + bg1); AS already holds split(xr)
    hgemm<<<gridG1, 256, HG_SMEM>>>(AS, KP3, WS1 + 7 * ws1slice, NPAD1, bg1,
                                    tmp, nullptr, nullptr, 0, NN, 600, KP3, 0);
    gate_kernel<<<(NN * 32 + 255) / 256, 256>>>(tmp, Wg2, bg2, gumbel, gate);

    // per-graph reductions
    segment_kernel<<<GG, 512>>>(hb, gate, batch, hr, henv, hout, rnum, envnum);
    norm_kernel<<<GG, 128>>>(hr, henv, hout, na, nb, nc, posdot);
    lossreg_kernel<<<1, 512>>>(rnum, envnum, out + 2 * GG * TASKS);

    // contrastive loss: S = hr @ henv^T (fp32: feeds exp(5*cos))
    transpose_kernel<<<(GG * EMB + 255) / 256, 256>>>(henv, henvT);
    dim3 gridS((GG + BN - 1) / BN, (GG + BM - 1) / BM);
    sgemm_opt<<<gridS, 256>>>(hr, henvT, S, GG, GG, EMB);
    rowsum_kernel<<<GG, 256>>>(S, na, nc, rowsum);
    losscon_kernel<<<1, 512>>>(posdot, na, nb, rowsum, out + 2 * GG * TASKS + 1);

    // prediction MLPs
    hin_kernel<<<(GG * EMB + 255) / 256, 256>>>(hr, henv, perm, hin);
    splitAB_kernel<<<(2 * GG * (EMB / 4) + 255) / 256, 256>>>(hin, nullptr, 2 * GG, AS);
    dim3 gridP(NPAD1 / 128, (2 * GG + 127) / 128);
    hgemm<<<gridP, 256, HG_SMEM>>>(AS, KP3, WS1 + 8 * ws1slice, NPAD1, bp1,
                                   tmp, nullptr, nullptr, 0, 2 * GG, 600, KP3, 0);
    pred2_kernel<<<(2 * GG * TASKS + 127) / 128, 128>>>(tmp, Wp2, bp2, out);
}